// round 2
// baseline (speedup 1.0000x reference)
#include <cuda_runtime.h>
#include <cuda_bf16.h>
#include <cstdint>

// BahdanauAttention: B=32, SK=8192, D=128  (compute_100-safe: mma.sync, no tcgen05)
//   t[b]       = q[b] @ W2                                  (K1)
//   logit[b,s] = Wf . tanh(K[b,s] @ W1 + t[b]) + bf         (K2, mma.sync bf16 3-split)
//   p = softmax_s(logit); attn[b] = sum_s p*v               (K3 + K4)
// Output layout: [attn (32*128) | attn_sm (32*8192)]

#define B_  32
#define SK_ 8192
#define D_  128

// ---------------- scratch (device globals; no allocs allowed) ----------------
__device__ float    g_t[B_ * D_];
__device__ uint4    g_W1hi4[D_ * D_ * 2 / 16];   // bf16 [k][n] hi
__device__ uint4    g_W1lo4[D_ * D_ * 2 / 16];   // bf16 [k][n] lo
__device__ float    g_logits[B_ * SK_];
__device__ unsigned g_maxkey[B_];
__device__ float    g_denom[B_];
__device__ float    g_acc[B_ * D_];

// ---------------- helpers ----------------
__device__ __forceinline__ uint32_t smem_u32(const void* p) {
    uint32_t r;
    asm("{ .reg .u64 t; cvta.to.shared.u64 t, %1; cvt.u32.u64 %0, t; }" : "=r"(r) : "l"(p));
    return r;
}
__device__ __forceinline__ float ex2f(float x) { float r; asm("ex2.approx.ftz.f32 %0, %1;" : "=f"(r) : "f"(x)); return r; }
__device__ __forceinline__ float rcpf(float x) { float r; asm("rcp.approx.ftz.f32 %0, %1;" : "=f"(r) : "f"(x)); return r; }
// tanh(x) = 1 - 2/(exp2(2*log2e*x)+1); correct at +-inf limits, rel err ~1e-6
__device__ __forceinline__ float tanh_fast(float x) {
    float e = ex2f(x * 2.885390081777927f);
    float r = rcpf(e + 1.0f);
    return fmaf(-2.0f, r, 1.0f);
}
// order-preserving float->uint key for atomicMax
__device__ __forceinline__ unsigned fkey(float f) {
    unsigned u = __float_as_uint(f);
    return (u & 0x80000000u) ? ~u : (u | 0x80000000u);
}
__device__ __forceinline__ float fkey_dec(unsigned k) {
    return (k & 0x80000000u) ? __uint_as_float(k & 0x7FFFFFFFu) : __uint_as_float(~k);
}
// split fp32 pair -> bf16x2 hi (low half = x0) + bf16x2 lo (residual)
__device__ __forceinline__ void split2(float x0, float x1, uint32_t& h, uint32_t& l) {
    asm("cvt.rn.bf16x2.f32 %0, %1, %2;" : "=r"(h) : "f"(x1), "f"(x0));
    float h0 = __uint_as_float(h << 16);
    float h1 = __uint_as_float(h & 0xFFFF0000u);
    float r0 = x0 - h0, r1 = x1 - h1;
    asm("cvt.rn.bf16x2.f32 %0, %1, %2;" : "=r"(l) : "f"(r1), "f"(r0));
}
__device__ __forceinline__ void ldsm_x4(uint32_t& r0, uint32_t& r1, uint32_t& r2, uint32_t& r3, uint32_t a) {
    asm volatile("ldmatrix.sync.aligned.m8n8.x4.shared.b16 {%0,%1,%2,%3}, [%4];"
                 : "=r"(r0), "=r"(r1), "=r"(r2), "=r"(r3) : "r"(a));
}
__device__ __forceinline__ void ldsm_x4_t(uint32_t& r0, uint32_t& r1, uint32_t& r2, uint32_t& r3, uint32_t a) {
    asm volatile("ldmatrix.sync.aligned.m8n8.x4.trans.shared.b16 {%0,%1,%2,%3}, [%4];"
                 : "=r"(r0), "=r"(r1), "=r"(r2), "=r"(r3) : "r"(a));
}
__device__ __forceinline__ void mma_bf16(float* c, uint32_t a0, uint32_t a1, uint32_t a2, uint32_t a3,
                                         uint32_t b0, uint32_t b1) {
    asm volatile("mma.sync.aligned.m16n8k16.row.col.f32.bf16.bf16.f32 "
                 "{%0,%1,%2,%3}, {%4,%5,%6,%7}, {%8,%9}, {%0,%1,%2,%3};"
                 : "+f"(c[0]), "+f"(c[1]), "+f"(c[2]), "+f"(c[3])
                 : "r"(a0), "r"(a1), "r"(a2), "r"(a3), "r"(b0), "r"(b1));
}

// ---------------- K1: prep ----------------
__global__ void __launch_bounds__(128) k1_prep(const float* __restrict__ q,
                                               const float* __restrict__ W2,
                                               const float* __restrict__ W1) {
    __shared__ float qs[128];
    int t = threadIdx.x, blk = blockIdx.x;
    if (blk < 32) {
        qs[t] = q[blk * 128 + t];
        __syncthreads();
        float a = 0.f;
        #pragma unroll 8
        for (int d = 0; d < 128; d++) a = fmaf(qs[d], W2[d * 128 + t], a);
        g_t[blk * 128 + t] = a;
        if (blk == 0 && t < 32) { g_maxkey[t] = 0x007FFFFFu; g_denom[t] = 0.f; }  // key(-inf)
    } else {
        int rb = blk - 32;  // 0..15: elementwise W1 split, natural [k][n] layout
        __nv_bfloat16* hi = (__nv_bfloat16*)g_W1hi4;
        __nv_bfloat16* lo = (__nv_bfloat16*)g_W1lo4;
        #pragma unroll
        for (int i = 0; i < 8; i++) {
            int o = rb * 1024 + i * 128 + t;
            float x = W1[o];
            __nv_bfloat16 h = __float2bfloat16(x);
            __nv_bfloat16 l = __float2bfloat16(x - __bfloat162float(h));
            hi[o] = h; lo[o] = l;
        }
        if (rb == 0) {
            #pragma unroll
            for (int i = 0; i < 32; i++) g_acc[i * 128 + t] = 0.f;
        }
    }
}

// ---------------- K2: fused GEMM (mma.sync) + tanh + Wf dot + per-batch max ----------------
// Tile: 64 seq rows x 128 n per CTA; 256 threads (8 warps): warp = (rowblk 0..3, nhalf 0..1)
// smem (padded row stride 272B = 128 bf16 + 16B pad for conflict-free ldmatrix)
#define KSTRIDE  272
#define OFF_T    0
#define OFF_WF   512
#define OFF_PART 1024
#define OFF_RED  1536
#define OFF_KHI  2048
#define OFF_KLO  (OFF_KHI + 64 * KSTRIDE)     // 19456
#define OFF_WHI  (OFF_KLO + 64 * KSTRIDE)     // 36864
#define OFF_WLO  (OFF_WHI + 128 * KSTRIDE)    // 71680
#define SMEM_TOT (OFF_WLO + 128 * KSTRIDE)    // 106496

__global__ void __launch_bounds__(256, 2) k2_gemm(const float* __restrict__ kk,
                                                  const float* __restrict__ wf,
                                                  const float* __restrict__ bf) {
    extern __shared__ char smem[];
    uint32_t sb = smem_u32(smem);
    int tid = threadIdx.x, wid = tid >> 5, lane = tid & 31;
    int b = blockIdx.y, tile = blockIdx.x;

    // broadcast vectors
    if (tid < 128)       ((float*)(smem + OFF_T))[tid]        = g_t[b * 128 + tid];
    else                 ((float*)(smem + OFF_WF))[tid - 128] = wf[tid - 128];

    // W1 hi/lo bf16 [k][n] -> smem (padded rows), coalesced 16B copies
    #pragma unroll
    for (int i = 0; i < 8; i++) {
        int gid = i * 256 + tid;            // 0..2047 uint4 per matrix
        int row = gid >> 4, c = gid & 15;
        *(uint4*)(smem + OFF_WHI + row * KSTRIDE + c * 16) = g_W1hi4[gid];
        *(uint4*)(smem + OFF_WLO + row * KSTRIDE + c * 16) = g_W1lo4[gid];
    }

    // K tile (64 x 128 fp32) -> split -> Khi/Klo bf16 smem
    const float4* kg = (const float4*)(kk + ((size_t)b * SK_ + (size_t)tile * 64) * 128);
    #pragma unroll
    for (int i = 0; i < 8; i++) {
        int gid = i * 256 + tid;            // 0..2047 float4
        int row = gid >> 5, c4 = gid & 31;  // col0 = c4*4
        float4 a = kg[gid];
        uint32_t h0, h1, l0, l1;
        split2(a.x, a.y, h0, l0);
        split2(a.z, a.w, h1, l1);
        *(uint2*)(smem + OFF_KHI + row * KSTRIDE + c4 * 8) = make_uint2(h0, h1);
        *(uint2*)(smem + OFF_KLO + row * KSTRIDE + c4 * 8) = make_uint2(l0, l1);
    }
    __syncthreads();

    // ---- MMA: 3 passes (Khi@Whi, Klo@Whi, Khi@Wlo) ----
    int rb = wid & 3, h = wid >> 2;
    float acc[8][4];
    #pragma unroll
    for (int j = 0; j < 8; j++)
        #pragma unroll
        for (int c = 0; c < 4; c++) acc[j][c] = 0.f;

    // A (non-trans x4): rows rb*16 + (lane&15), k byte off = kc*32 + (lane>>4)*16
    uint32_t a_off = (uint32_t)(rb * 16 + (lane & 15)) * KSTRIDE + (uint32_t)(lane >> 4) * 16;
    // B (trans x4): k rows (lane&15) + kc*16, n byte off = h*128 + j4*32 + (lane>>4)*16
    uint32_t b_off = (uint32_t)(lane & 15) * KSTRIDE + (uint32_t)h * 128 + (uint32_t)(lane >> 4) * 16;

    uint32_t asrc[3] = { sb + OFF_KHI, sb + OFF_KLO, sb + OFF_KHI };
    uint32_t bsrc[3] = { sb + OFF_WHI, sb + OFF_WHI, sb + OFF_WLO };

    #pragma unroll
    for (int p = 0; p < 3; p++) {
        uint32_t abase = asrc[p] + a_off;
        uint32_t bbase = bsrc[p] + b_off;
        #pragma unroll
        for (int kc = 0; kc < 8; kc++) {
            uint32_t a0, a1, a2, a3;
            ldsm_x4(a0, a1, a2, a3, abase + kc * 32);
            #pragma unroll
            for (int j4 = 0; j4 < 4; j4++) {
                uint32_t b0, b1, b2, b3;
                ldsm_x4_t(b0, b1, b2, b3, bbase + kc * (16 * KSTRIDE) + j4 * 32);
                mma_bf16(acc[2 * j4],     a0, a1, a2, a3, b0, b1);
                mma_bf16(acc[2 * j4 + 1], a0, a1, a2, a3, b2, b3);
            }
        }
    }

    // ---- epilogue: z = acc + t[col]; dot(tanh(z), wf) over this warp's 64 cols ----
    const float* t_sm  = (const float*)(smem + OFF_T);
    const float* wf_sm = (const float*)(smem + OFF_WF);
    float slow = 0.f, shigh = 0.f;
    #pragma unroll
    for (int j = 0; j < 8; j++) {
        int c0 = h * 64 + j * 8 + 2 * (lane & 3);
        float t0 = t_sm[c0], t1 = t_sm[c0 + 1];
        float w0 = wf_sm[c0], w1 = wf_sm[c0 + 1];
        slow  = fmaf(tanh_fast(acc[j][0] + t0), w0, slow);
        slow  = fmaf(tanh_fast(acc[j][1] + t1), w1, slow);
        shigh = fmaf(tanh_fast(acc[j][2] + t0), w0, shigh);
        shigh = fmaf(tanh_fast(acc[j][3] + t1), w1, shigh);
    }
    // reduce over the 4 lanes sharing each row
    #pragma unroll
    for (int s = 1; s <= 2; s <<= 1) {
        slow  += __shfl_xor_sync(0xffffffffu, slow,  s);
        shigh += __shfl_xor_sync(0xffffffffu, shigh, s);
    }
    float* part = (float*)(smem + OFF_PART);   // part[h][row], 2 x 64
    if ((lane & 3) == 0) {
        int row = rb * 16 + (lane >> 2);
        part[h * 64 + row]     = slow;
        part[h * 64 + row + 8] = shigh;
    }
    __syncthreads();

    float logit = -3.402823466e38f;
    if (tid < 64) {
        logit = part[tid] + part[64 + tid] + bf[0];
        g_logits[(size_t)b * SK_ + (size_t)tile * 64 + tid] = logit;
    }
    // block max (only tids 0..63 hold real logits) -> atomicMax per batch
    float m = logit;
    #pragma unroll
    for (int s = 16; s > 0; s >>= 1) m = fmaxf(m, __shfl_xor_sync(0xffffffffu, m, s));
    float* red = (float*)(smem + OFF_RED);
    if (tid < 64 && lane == 0) red[wid] = m;
    __syncthreads();
    if (tid == 0) atomicMax(&g_maxkey[b], fkey(fmaxf(red[0], red[1])));
}

// ---------------- K3: exp + denom + weighted V accumulation ----------------
__global__ void __launch_bounds__(256) k3_softv(const float* __restrict__ v,
                                                float* __restrict__ out) {
    __shared__ float e_sm[512];
    __shared__ float red[8];
    __shared__ float part2[128];
    int t = threadIdx.x;
    int b = blockIdx.y, ch = blockIdx.x;
    float mx = fkey_dec(g_maxkey[b]);
    size_t base = (size_t)b * SK_ + (size_t)ch * 512;

    float lsum = 0.f;
    #pragma unroll
    for (int i = 0; i < 2; i++) {
        int s = i * 256 + t;
        float l = g_logits[base + s];
        float e = ex2f((l - mx) * 1.4426950408889634f);
        e_sm[s] = e;
        out[4096 + base + s] = e;     // unnormalized; K4 rescales
        lsum += e;
    }
    #pragma unroll
    for (int s = 16; s > 0; s >>= 1) lsum += __shfl_xor_sync(0xffffffffu, lsum, s);
    if ((t & 31) == 0) red[t >> 5] = lsum;
    __syncthreads();
    if (t == 0) {
        float s = 0.f;
        #pragma unroll
        for (int i = 0; i < 8; i++) s += red[i];
        atomicAdd(&g_denom[b], s);
    }

    int d = t & 127, g = t >> 7;
    const float* vb = v + base * 128;
    float acc = 0.f;
    #pragma unroll 4
    for (int s = g; s < 512; s += 2)
        acc = fmaf(e_sm[s], vb[(size_t)s * 128 + d], acc);
    if (g == 1) part2[d] = acc;
    __syncthreads();
    if (g == 0) atomicAdd(&g_acc[b * 128 + d], acc + part2[d]);
}

// ---------------- K4: normalize ----------------
__global__ void __launch_bounds__(256) k4_final(float* __restrict__ out, int out_size) {
    int i = blockIdx.x * blockDim.x + threadIdx.x;
    if (i >= out_size) return;
    if (i < 4096) {
        int b = i >> 7;
        out[i] = g_acc[i] / g_denom[b];
    } else {
        int b = (i - 4096) >> 13;
        out[i] = out[i] / g_denom[b];
    }
}

// ---------------- launch ----------------
extern "C" void kernel_launch(void* const* d_in, const int* in_sizes, int n_in,
                              void* d_out, int out_size) {
    const float* q  = (const float*)d_in[0];
    const float* kk = (const float*)d_in[1];
    const float* v  = (const float*)d_in[2];
    const float* W1 = (const float*)d_in[3];
    const float* W2 = (const float*)d_in[4];
    const float* Wf = (const float*)d_in[5];
    const float* bf = (const float*)d_in[6];
    float* out = (float*)d_out;

    cudaFuncSetAttribute(k2_gemm, cudaFuncAttributeMaxDynamicSharedMemorySize, SMEM_TOT);

    k1_prep<<<48, 128>>>(q, W2, W1);
    k2_gemm<<<dim3(128, 32), 256, SMEM_TOT>>>(kk, Wf, bf);
    k3_softv<<<dim3(16, 32), 256>>>(v, out);
    k4_final<<<(out_size + 255) / 256, 256>>>(out, out_size);
}